// round 4
// baseline (speedup 1.0000x reference)
#include <cuda_runtime.h>
#include <cuda_bf16.h>
#include <math.h>
#include <stdint.h>

#define NN 100000
#define NE 500000
#define DIMC 256
#define NH 8

// ---------------------------------------------------------------------------
// Device-global scratch (no allocation allowed in kernel_launch)
// ---------------------------------------------------------------------------
__device__ float g_Q[NN * DIMC];
__device__ float g_K[NN * DIMC];
__device__ float g_V[NN * DIMC];
__device__ float g_wV[NN * DIMC];
__device__ float g_Z[NN * NH];
__device__ float g_cs[DIMC];
__device__ float g_cs2[DIMC];
__device__ int g_src[NE];
__device__ int g_dst[NE];
__device__ __nv_bfloat16 g_Wh[768 * DIMC], g_Wl[768 * DIMC];     // [n][k], QKV concat
__device__ __nv_bfloat16 g_WEh[DIMC * DIMC], g_WEl[DIMC * DIMC]; // [n][k]

// ---------------------------------------------------------------------------
// Warp-MMA helpers (portable PTX: ldmatrix + mma.sync, sm_80+ features)
// ---------------------------------------------------------------------------
__device__ __forceinline__ uint32_t smem_u32(const void* p) {
    uint32_t a;
    asm("{ .reg .u64 t; cvta.to.shared.u64 t, %1; cvt.u32.u64 %0, t; }"
        : "=r"(a) : "l"(p));
    return a;
}
__device__ __forceinline__ void ldsm_x4(uint32_t* r, uint32_t addr) {
    asm volatile("ldmatrix.sync.aligned.m8n8.x4.shared.b16 {%0,%1,%2,%3}, [%4];"
                 : "=r"(r[0]), "=r"(r[1]), "=r"(r[2]), "=r"(r[3]) : "r"(addr));
}
__device__ __forceinline__ void ldsm_x2(uint32_t* r, uint32_t addr) {
    asm volatile("ldmatrix.sync.aligned.m8n8.x2.shared.b16 {%0,%1}, [%2];"
                 : "=r"(r[0]), "=r"(r[1]) : "r"(addr));
}
__device__ __forceinline__ void mma_bf16(float* d, const uint32_t* a, const uint32_t* b) {
    asm volatile(
        "mma.sync.aligned.m16n8k16.row.col.f32.bf16.bf16.f32 "
        "{%0,%1,%2,%3}, {%4,%5,%6,%7}, {%8,%9}, {%0,%1,%2,%3};"
        : "+f"(d[0]), "+f"(d[1]), "+f"(d[2]), "+f"(d[3])
        : "r"(a[0]), "r"(a[1]), "r"(a[2]), "r"(a[3]), "r"(b[0]), "r"(b[1]));
}
__device__ __forceinline__ uint32_t packbf(__nv_bfloat16 a, __nv_bfloat16 b) {
    __nv_bfloat162 t = __halves2bfloat162(a, b);
    return *(uint32_t*)&t;
}

// ---------------------------------------------------------------------------
// Zero atomically-updated accumulators.
// ---------------------------------------------------------------------------
__global__ void zero_kernel() {
    long total = (long)NN * DIMC + (long)NN * NH;
    long stride = (long)gridDim.x * blockDim.x;
    for (long i = (long)blockIdx.x * blockDim.x + threadIdx.x; i < total; i += stride) {
        if (i < (long)NN * DIMC) g_wV[i] = 0.0f;
        else                     g_Z[i - (long)NN * DIMC] = 0.0f;
    }
    if (blockIdx.x == 0 && threadIdx.x < DIMC) {
        g_cs[threadIdx.x]  = 0.0f;
        g_cs2[threadIdx.x] = 0.0f;
    }
}

// ---------------------------------------------------------------------------
// edge_index -> int32 src/dst (handles int64 or int32 payload, deterministic)
// ---------------------------------------------------------------------------
__global__ void cvt_idx_kernel(const long long* __restrict__ e64) {
    const int* e32 = (const int*)e64;
    bool is64 = true;
    #pragma unroll
    for (int i = 0; i < 64; ++i)
        if ((e64[i] >> 32) != 0) is64 = false;
    long stride = (long)gridDim.x * blockDim.x;
    for (long e = (long)blockIdx.x * blockDim.x + threadIdx.x; e < NE; e += stride) {
        if (is64) { g_src[e] = (int)e64[e]; g_dst[e] = (int)e64[NE + e]; }
        else      { g_src[e] = e32[e];      g_dst[e] = e32[NE + e];      }
    }
}

// ---------------------------------------------------------------------------
// Weights transposed into B-operand layout [n][k], split hi/lo. (Tiny.)
// ---------------------------------------------------------------------------
__global__ void prep_w_kernel(const float* __restrict__ WQ, const float* __restrict__ WK,
                              const float* __restrict__ WV, const float* __restrict__ WE) {
    int i = blockIdx.x * 256 + threadIdx.x;   // 0 .. 1024*256-1
    if (i < 768 * DIMC) {
        int n = i >> 8;
        int k = i & 255;
        int m = n >> 8, nn = n & 255;
        const float* W = (m == 0) ? WQ : (m == 1) ? WK : WV;
        float v = W[k * DIMC + nn];
        __nv_bfloat16 h = __float2bfloat16(v);
        g_Wh[i] = h;
        g_Wl[i] = __float2bfloat16(v - __bfloat162float(h));
    } else {
        int j = i - 768 * DIMC;
        int n = j >> 8, k = j & 255;
        float v = WE[k * DIMC + n];
        __nv_bfloat16 h = __float2bfloat16(v);
        g_WEh[j] = h;
        g_WEl[j] = __float2bfloat16(v - __bfloat162float(h));
    }
}

// ---------------------------------------------------------------------------
// Warp-MMA split-bf16 GEMM, 128x128 block tile, K=256 in 8 chunks of 32.
// A read as raw fp32 and converted to hi/lo bf16 during staging (no prep pass).
// 8 warps in 4(M) x 2(N); each warp computes 32x64 via m16n8k16 bf16 mma.
// 3 MMAs per (mi,ni,k16): Ah*Bh + Ah*Bl + Al*Bh  (fp32 accumulate).
// EDGE=0: writes Q/K/V.
// EDGE=1: fused per-edge head-score epilogue + in-kernel V scatter/Z atomics.
// ---------------------------------------------------------------------------
template<int EDGE>
__global__ void __launch_bounds__(256, 2) mma_gemm_kernel(const float* __restrict__ Asrc) {
    // smem tiles padded to 40 bf16 per row (80B) -> conflict-free ldmatrix
    __shared__ __align__(16) __nv_bfloat16 sAh[128 * 40];
    __shared__ __align__(16) __nv_bfloat16 sAl[128 * 40];
    __shared__ __align__(16) __nv_bfloat16 sBh[128 * 40];
    __shared__ __align__(16) __nv_bfloat16 sBl[128 * 40];
    __shared__ int Ssrc[128], Sdst[128];
    __shared__ float sS[128][4];     // per-edge scores for this tile's 4 heads

    const int tid  = threadIdx.x;
    const int wid  = tid >> 5;
    const int lane = tid & 31;
    const int wm   = wid & 3;    // 4 M-groups of 32 rows
    const int wn   = wid >> 2;   // 2 N-groups of 64 cols
    const int quad = lane & 3;
    const int qrow = lane >> 2;

    const int row0  = blockIdx.x * 128;
    const int nbase = blockIdx.y * 128;
    const int Mtot  = EDGE ? NE : NN;

    if (EDGE && tid < 128) {
        int ge = row0 + tid;
        if (ge > NE - 1) ge = NE - 1;
        Ssrc[tid] = g_src[ge];
        Sdst[tid] = g_dst[ge];
    }

    const float4* A4 = (const float4*)Asrc;
    const uint4* Bh4 = EDGE ? (const uint4*)g_WEh : (const uint4*)g_Wh;
    const uint4* Bl4 = EDGE ? (const uint4*)g_WEl : (const uint4*)g_Wl;

    float acc[2][8][4] = {};

    const uint32_t bAh = smem_u32(sAh), bAl = smem_u32(sAl);
    const uint32_t bBh = smem_u32(sBh), bBl = smem_u32(sBl);
    const uint32_t aOff = (uint32_t)((wm * 32 + (lane & 15)) * 80 + (lane >> 4) * 16);
    const uint32_t bOffRow = (uint32_t)((wn * 64 + (lane & 7)) * 80 + ((lane >> 3) & 1) * 16);

    for (int kc = 0; kc < 8; ++kc) {
        __syncthreads();
        // A chunk: 128 rows x 32 fp32 cols = 1024 float4; convert to hi/lo bf16.
        #pragma unroll
        for (int l = 0; l < 4; ++l) {
            int idx = tid + l * 256;
            int row = idx >> 3;
            int c4  = idx & 7;
            long rowg = min(row0 + row, Mtot - 1);
            float4 v = A4[rowg * 64 + kc * 8 + c4];
            __nv_bfloat16 h0 = __float2bfloat16(v.x);
            __nv_bfloat16 h1 = __float2bfloat16(v.y);
            __nv_bfloat16 h2 = __float2bfloat16(v.z);
            __nv_bfloat16 h3 = __float2bfloat16(v.w);
            __nv_bfloat16 l0 = __float2bfloat16(v.x - __bfloat162float(h0));
            __nv_bfloat16 l1 = __float2bfloat16(v.y - __bfloat162float(h1));
            __nv_bfloat16 l2 = __float2bfloat16(v.z - __bfloat162float(h2));
            __nv_bfloat16 l3 = __float2bfloat16(v.w - __bfloat162float(h3));
            *(uint2*)(sAh + row * 40 + c4 * 4) = make_uint2(packbf(h0, h1), packbf(h2, h3));
            *(uint2*)(sAl + row * 40 + c4 * 4) = make_uint2(packbf(l0, l1), packbf(l2, l3));
        }
        // B chunk: Bh/Bl 128x32 bf16 each (512 uint4 each).
        #pragma unroll
        for (int l = 0; l < 4; ++l) {
            int idx = tid + l * 256;
            int sel = idx >> 9;
            int w   = idx & 511;
            int row = w >> 2;
            int c4  = w & 3;
            uint4 v = (sel ? Bl4 : Bh4)[(long)(nbase + row) * 32 + kc * 4 + c4];
            *(uint4*)((sel ? sBl : sBh) + row * 40 + c4 * 8) = v;
        }
        __syncthreads();

        #pragma unroll
        for (int s = 0; s < 2; ++s) {
            uint32_t ah[2][4], al[2][4];
            #pragma unroll
            for (int mi = 0; mi < 2; ++mi) {
                uint32_t o = aOff + (uint32_t)(mi * 16 * 80 + s * 32);
                ldsm_x4(ah[mi], bAh + o);
                ldsm_x4(al[mi], bAl + o);
            }
            #pragma unroll
            for (int ni = 0; ni < 8; ++ni) {
                uint32_t bo = bOffRow + (uint32_t)(ni * 8 * 80 + s * 32);
                uint32_t bh[2], bl[2];
                ldsm_x2(bh, bBh + bo);
                ldsm_x2(bl, bBl + bo);
                #pragma unroll
                for (int mi = 0; mi < 2; ++mi) {
                    mma_bf16(acc[mi][ni], ah[mi], bh);
                    mma_bf16(acc[mi][ni], ah[mi], bl);
                    mma_bf16(acc[mi][ni], al[mi], bh);
                }
            }
        }
    }

    if (EDGE) {
        // Per-edge head scores for this tile's 4 heads -> sS.
        const float scale = 0.17677669529663687f;  // 1/sqrt(32)
        #pragma unroll
        for (int mi = 0; mi < 2; ++mi) {
            #pragma unroll
            for (int rh = 0; rh < 2; ++rh) {
                int r = wm * 32 + mi * 16 + qrow + rh * 8;
                const float* Kr = g_K + (long)Ssrc[r] * DIMC + nbase + wn * 64;
                const float* Qr = g_Q + (long)Sdst[r] * DIMC + nbase + wn * 64;
                #pragma unroll
                for (int h = 0; h < 2; ++h) {
                    float p = 0.0f;
                    #pragma unroll
                    for (int j = 0; j < 4; ++j) {
                        int ni = h * 4 + j;
                        int c  = ni * 8 + quad * 2;
                        float2 kv = *(const float2*)(Kr + c);
                        float2 qv = *(const float2*)(Qr + c);
                        p += acc[mi][ni][rh * 2 + 0] * kv.x * qv.x;
                        p += acc[mi][ni][rh * 2 + 1] * kv.y * qv.y;
                    }
                    p += __shfl_xor_sync(0xffffffffu, p, 1);
                    p += __shfl_xor_sync(0xffffffffu, p, 2);
                    if (quad == 0) {
                        float sv = fminf(5.0f, fmaxf(-5.0f, p * scale));
                        sS[r][wn * 2 + h] = expf(sv);
                    }
                }
            }
        }
        __syncthreads();

        // In-kernel scatter for this tile's 128 columns (4 heads).
        // thread -> col (tid&127), half of the 128 edges (tid>>7).
        {
            int c  = tid & 127;
            int ht = c >> 5;
            int e_lo = (tid >> 7) * 64;
            #pragma unroll 4
            for (int el = e_lo; el < e_lo + 64; ++el) {
                int ge = row0 + el;
                if (ge < NE) {
                    float s = sS[el][ht];
                    atomicAdd(&g_wV[(long)Sdst[el] * DIMC + nbase + c],
                              g_V[(long)Ssrc[el] * DIMC + nbase + c] * s);
                }
            }
        }
        // Z atomics for this tile's 4 heads: 128 edges x 4 = 512 adds.
        for (int p = tid; p < 512; p += 256) {
            int el = p >> 2, ht2 = p & 3;
            int ge = row0 + el;
            if (ge < NE)
                atomicAdd(&g_Z[(long)Sdst[el] * NH + (nbase >> 5) + ht2], sS[el][ht2]);
        }
    } else {
        int by = blockIdx.y;
        float* Cout = (by < 2) ? g_Q : (by < 4) ? g_K : g_V;
        int colb = (by & 1) * 128;
        #pragma unroll
        for (int mi = 0; mi < 2; ++mi) {
            #pragma unroll
            for (int ni = 0; ni < 8; ++ni) {
                int r = row0 + wm * 32 + mi * 16 + qrow;
                int c = colb + wn * 64 + ni * 8 + quad * 2;
                if (r < NN)
                    *(float2*)(Cout + (long)r * DIMC + c) =
                        make_float2(acc[mi][ni][0], acc[mi][ni][1]);
                if (r + 8 < NN)
                    *(float2*)(Cout + (long)(r + 8) * DIMC + c) =
                        make_float2(acc[mi][ni][2], acc[mi][ni][3]);
            }
        }
    }
}

// ---------------------------------------------------------------------------
// Residual + BN column stats, then normalize.
// ---------------------------------------------------------------------------
__global__ void resid_stats_kernel(const float* __restrict__ x, float* __restrict__ out) {
    int c = threadIdx.x;
    int r0 = blockIdx.x * 256;
    int rend = min(NN, r0 + 256);
    float s = 0.0f, s2 = 0.0f;
    for (int n = r0; n < rend; ++n) {
        float z = g_Z[(long)n * NH + (c >> 5)] + 1e-6f;
        float h = x[(long)n * DIMC + c] + g_wV[(long)n * DIMC + c] / z;
        out[(long)n * DIMC + c] = h;
        s += h;
        s2 += h * h;
    }
    atomicAdd(&g_cs[c], s);
    atomicAdd(&g_cs2[c], s2);
}

__global__ void bn_norm_kernel(float* __restrict__ out,
                               const float* __restrict__ gamma,
                               const float* __restrict__ beta) {
    long total = (long)NN * DIMC;
    long stride = (long)gridDim.x * blockDim.x;
    const float invN = 1.0f / (float)NN;
    for (long i = (long)blockIdx.x * blockDim.x + threadIdx.x; i < total; i += stride) {
        int c = (int)(i & (DIMC - 1));
        float mean = g_cs[c] * invN;
        float var = g_cs2[c] * invN - mean * mean;
        out[i] = (out[i] - mean) * rsqrtf(var + 1e-5f) * gamma[c] + beta[c];
    }
}

extern "C" void kernel_launch(void* const* d_in, const int* in_sizes, int n_in,
                              void* d_out, int out_size) {
    const float* x     = (const float*)d_in[0];
    const float* ea    = (const float*)d_in[1];
    const float* WQ    = (const float*)d_in[2];
    const float* WK    = (const float*)d_in[3];
    const float* WE    = (const float*)d_in[4];
    const float* WV    = (const float*)d_in[5];
    const float* gamma = (const float*)d_in[6];
    const float* beta  = (const float*)d_in[7];
    const long long* eidx = (const long long*)d_in[8];
    float* out = (float*)d_out;

    zero_kernel<<<1024, 256>>>();
    cvt_idx_kernel<<<512, 256>>>(eidx);
    prep_w_kernel<<<1024, 256>>>(WQ, WK, WV, WE);

    // QKV: C[100000,768] -> 782 x 6 tiles of 128x128 (A = x, converted in-kernel)
    mma_gemm_kernel<0><<<dim3(782, 6), 256>>>(x);
    // Edge: Eh GEMM + fused score epilogue + fused V/Z scatter -> 3907 x 2 tiles
    mma_gemm_kernel<1><<<dim3(3907, 2), 256>>>(ea);

    resid_stats_kernel<<<(NN + 255) / 256, 256>>>(x, out);
    bn_norm_kernel<<<2048, 256>>>(out, gamma, beta);
}

// round 5
// speedup vs baseline: 1.4412x; 1.4412x over previous
#include <cuda_runtime.h>
#include <cuda_bf16.h>
#include <math.h>
#include <stdint.h>

#define NN 100000
#define NE 500000
#define DIMC 256
#define NH 8

// ---------------------------------------------------------------------------
// Device-global scratch (no allocation allowed in kernel_launch)
// ---------------------------------------------------------------------------
__device__ float g_Q[NN * DIMC];
__device__ float g_K[NN * DIMC];
__device__ float g_V[NN * DIMC];
__device__ float g_wV[NN * DIMC];
__device__ float g_Z[NN * NH];
__device__ float g_S[NE * NH];
__device__ float g_cs[DIMC];
__device__ float g_cs2[DIMC];
__device__ int g_src[NE];
__device__ int g_dst[NE];
__device__ __nv_bfloat16 g_Wh[768 * DIMC], g_Wl[768 * DIMC];     // [n][k], QKV concat
__device__ __nv_bfloat16 g_WEh[DIMC * DIMC], g_WEl[DIMC * DIMC]; // [n][k]

// ---------------------------------------------------------------------------
// Warp-MMA helpers (portable PTX: ldmatrix + mma.sync + cp.async, sm_80+)
// ---------------------------------------------------------------------------
__device__ __forceinline__ uint32_t smem_u32(const void* p) {
    uint32_t a;
    asm("{ .reg .u64 t; cvta.to.shared.u64 t, %1; cvt.u32.u64 %0, t; }"
        : "=r"(a) : "l"(p));
    return a;
}
__device__ __forceinline__ void ldsm_x4(uint32_t* r, uint32_t addr) {
    asm volatile("ldmatrix.sync.aligned.m8n8.x4.shared.b16 {%0,%1,%2,%3}, [%4];"
                 : "=r"(r[0]), "=r"(r[1]), "=r"(r[2]), "=r"(r[3]) : "r"(addr));
}
__device__ __forceinline__ void ldsm_x2(uint32_t* r, uint32_t addr) {
    asm volatile("ldmatrix.sync.aligned.m8n8.x2.shared.b16 {%0,%1}, [%2];"
                 : "=r"(r[0]), "=r"(r[1]) : "r"(addr));
}
__device__ __forceinline__ void mma_bf16(float* d, const uint32_t* a, const uint32_t* b) {
    asm volatile(
        "mma.sync.aligned.m16n8k16.row.col.f32.bf16.bf16.f32 "
        "{%0,%1,%2,%3}, {%4,%5,%6,%7}, {%8,%9}, {%0,%1,%2,%3};"
        : "+f"(d[0]), "+f"(d[1]), "+f"(d[2]), "+f"(d[3])
        : "r"(a[0]), "r"(a[1]), "r"(a[2]), "r"(a[3]), "r"(b[0]), "r"(b[1]));
}
__device__ __forceinline__ uint32_t packbf(__nv_bfloat16 a, __nv_bfloat16 b) {
    __nv_bfloat162 t = __halves2bfloat162(a, b);
    return *(uint32_t*)&t;
}
__device__ __forceinline__ void cp_async16(uint32_t saddr, const void* gptr) {
    asm volatile("cp.async.cg.shared.global [%0], [%1], 16;"
                 :: "r"(saddr), "l"(gptr) : "memory");
}
__device__ __forceinline__ void cp_async_wait_all() {
    asm volatile("cp.async.commit_group;\n\tcp.async.wait_group 0;" ::: "memory");
}

// ---------------------------------------------------------------------------
// Zero atomically-updated accumulators.
// ---------------------------------------------------------------------------
__global__ void zero_kernel() {
    long total = (long)NN * DIMC + (long)NN * NH;
    long stride = (long)gridDim.x * blockDim.x;
    for (long i = (long)blockIdx.x * blockDim.x + threadIdx.x; i < total; i += stride) {
        if (i < (long)NN * DIMC) g_wV[i] = 0.0f;
        else                     g_Z[i - (long)NN * DIMC] = 0.0f;
    }
    if (blockIdx.x == 0 && threadIdx.x < DIMC) {
        g_cs[threadIdx.x]  = 0.0f;
        g_cs2[threadIdx.x] = 0.0f;
    }
}

// ---------------------------------------------------------------------------
// edge_index -> int32 src/dst (handles int64 or int32 payload, deterministic)
// ---------------------------------------------------------------------------
__global__ void cvt_idx_kernel(const long long* __restrict__ e64) {
    const int* e32 = (const int*)e64;
    bool is64 = true;
    #pragma unroll
    for (int i = 0; i < 64; ++i)
        if ((e64[i] >> 32) != 0) is64 = false;
    long stride = (long)gridDim.x * blockDim.x;
    for (long e = (long)blockIdx.x * blockDim.x + threadIdx.x; e < NE; e += stride) {
        if (is64) { g_src[e] = (int)e64[e]; g_dst[e] = (int)e64[NE + e]; }
        else      { g_src[e] = e32[e];      g_dst[e] = e32[NE + e];      }
    }
}

// ---------------------------------------------------------------------------
// Weights transposed into B-operand layout [n][k], split hi/lo. (Tiny.)
// ---------------------------------------------------------------------------
__global__ void prep_w_kernel(const float* __restrict__ WQ, const float* __restrict__ WK,
                              const float* __restrict__ WV, const float* __restrict__ WE) {
    int i = blockIdx.x * 256 + threadIdx.x;   // 0 .. 1024*256-1
    if (i < 768 * DIMC) {
        int n = i >> 8;
        int k = i & 255;
        int m = n >> 8, nn = n & 255;
        const float* W = (m == 0) ? WQ : (m == 1) ? WK : WV;
        float v = W[k * DIMC + nn];
        __nv_bfloat16 h = __float2bfloat16(v);
        g_Wh[i] = h;
        g_Wl[i] = __float2bfloat16(v - __bfloat162float(h));
    } else {
        int j = i - 768 * DIMC;
        int n = j >> 8, k = j & 255;
        float v = WE[k * DIMC + n];
        __nv_bfloat16 h = __float2bfloat16(v);
        g_WEh[j] = h;
        g_WEl[j] = __float2bfloat16(v - __bfloat162float(h));
    }
}

// ---------------------------------------------------------------------------
// Warp-MMA split-bf16 GEMM, 128x128 block tile, K=256 in 8 chunks of 32.
// A read as raw fp32, register-prefetched one chunk ahead, converted to hi/lo
// bf16 at STS time. B staged via cp.async (L2-resident weights, no reg cost).
// 8 warps in 4(M) x 2(N); each warp computes 32x64 via m16n8k16 bf16 mma.
// 3 MMAs per (mi,ni,k16): Ah*Bh + Ah*Bl + Al*Bh  (fp32 accumulate).
// EDGE=0: writes Q/K/V.  EDGE=1: per-edge head-score epilogue -> g_S.
// ---------------------------------------------------------------------------
template<int EDGE>
__global__ void __launch_bounds__(256, 2) mma_gemm_kernel(const float* __restrict__ Asrc) {
    __shared__ __align__(16) __nv_bfloat16 sAh[128 * 40];
    __shared__ __align__(16) __nv_bfloat16 sAl[128 * 40];
    __shared__ __align__(16) __nv_bfloat16 sBh[128 * 40];
    __shared__ __align__(16) __nv_bfloat16 sBl[128 * 40];
    __shared__ int Ssrc[128], Sdst[128];

    const int tid  = threadIdx.x;
    const int wid  = tid >> 5;
    const int lane = tid & 31;
    const int wm   = wid & 3;
    const int wn   = wid >> 2;
    const int quad = lane & 3;
    const int qrow = lane >> 2;

    const int row0  = blockIdx.x * 128;
    const int nbase = blockIdx.y * 128;
    const int Mtot  = EDGE ? NE : NN;

    if (EDGE && tid < 128) {
        int ge = row0 + tid;
        if (ge > NE - 1) ge = NE - 1;
        Ssrc[tid] = g_src[ge];
        Sdst[tid] = g_dst[ge];
    }

    const float4* A4 = (const float4*)Asrc;
    const uint4* Bh4 = EDGE ? (const uint4*)g_WEh : (const uint4*)g_Wh;
    const uint4* Bl4 = EDGE ? (const uint4*)g_WEl : (const uint4*)g_Wl;

    float acc[2][8][4] = {};

    const uint32_t bAh = smem_u32(sAh), bAl = smem_u32(sAl);
    const uint32_t bBh = smem_u32(sBh), bBl = smem_u32(sBl);
    const uint32_t aOff = (uint32_t)((wm * 32 + (lane & 15)) * 80 + (lane >> 4) * 16);
    const uint32_t bOffRow = (uint32_t)((wn * 64 + (lane & 7)) * 80 + ((lane >> 3) & 1) * 16);

    // Per-thread fixed staging coordinates.
    // A: l in [0,4): idx = tid + l*256; row = idx>>3; c4 = idx&7.
    const int aRow[4] = { (tid + 0) >> 3, (tid + 256) >> 3, (tid + 512) >> 3, (tid + 768) >> 3 };
    const int aC4 = tid & 7;
    long aRowG[4];
    #pragma unroll
    for (int l = 0; l < 4; ++l) aRowG[l] = min(row0 + aRow[l], Mtot - 1);

    // Prefetch A chunk 0.
    float4 aPre[4];
    #pragma unroll
    for (int l = 0; l < 4; ++l) aPre[l] = A4[aRowG[l] * 64 + 0 + aC4];

    for (int kc = 0; kc < 8; ++kc) {
        __syncthreads();   // previous chunk's consumers done
        // Store prefetched A (convert fp32 -> hi/lo bf16).
        #pragma unroll
        for (int l = 0; l < 4; ++l) {
            float4 v = aPre[l];
            __nv_bfloat16 h0 = __float2bfloat16(v.x);
            __nv_bfloat16 h1 = __float2bfloat16(v.y);
            __nv_bfloat16 h2 = __float2bfloat16(v.z);
            __nv_bfloat16 h3 = __float2bfloat16(v.w);
            __nv_bfloat16 l0 = __float2bfloat16(v.x - __bfloat162float(h0));
            __nv_bfloat16 l1 = __float2bfloat16(v.y - __bfloat162float(h1));
            __nv_bfloat16 l2 = __float2bfloat16(v.z - __bfloat162float(h2));
            __nv_bfloat16 l3 = __float2bfloat16(v.w - __bfloat162float(h3));
            int row = aRow[l];
            *(uint2*)(sAh + row * 40 + aC4 * 4) = make_uint2(packbf(h0, h1), packbf(h2, h3));
            *(uint2*)(sAl + row * 40 + aC4 * 4) = make_uint2(packbf(l0, l1), packbf(l2, l3));
        }
        // B via cp.async (bypasses RF; weights are L2-resident).
        #pragma unroll
        for (int l = 0; l < 4; ++l) {
            int idx = tid + l * 256;
            int sel = idx >> 9;
            int w   = idx & 511;
            int row = w >> 2;
            int c4  = w & 3;
            const uint4* gsrc = (sel ? Bl4 : Bh4) + (long)(nbase + row) * 32 + kc * 4 + c4;
            uint32_t sdst = (sel ? bBl : bBh) + (uint32_t)(row * 80 + c4 * 16);
            cp_async16(sdst, gsrc);
        }
        cp_async_wait_all();
        __syncthreads();

        // Prefetch next A chunk: LDGs fly during the MMA section below.
        if (kc < 7) {
            #pragma unroll
            for (int l = 0; l < 4; ++l)
                aPre[l] = A4[aRowG[l] * 64 + (kc + 1) * 8 + aC4];
        }

        #pragma unroll
        for (int s = 0; s < 2; ++s) {
            uint32_t ah[2][4], al[2][4];
            #pragma unroll
            for (int mi = 0; mi < 2; ++mi) {
                uint32_t o = aOff + (uint32_t)(mi * 16 * 80 + s * 32);
                ldsm_x4(ah[mi], bAh + o);
                ldsm_x4(al[mi], bAl + o);
            }
            #pragma unroll
            for (int ni = 0; ni < 8; ++ni) {
                uint32_t bo = bOffRow + (uint32_t)(ni * 8 * 80 + s * 32);
                uint32_t bh[2], bl[2];
                ldsm_x2(bh, bBh + bo);
                ldsm_x2(bl, bBl + bo);
                #pragma unroll
                for (int mi = 0; mi < 2; ++mi) {
                    mma_bf16(acc[mi][ni], ah[mi], bh);
                    mma_bf16(acc[mi][ni], ah[mi], bl);
                    mma_bf16(acc[mi][ni], al[mi], bh);
                }
            }
        }
    }

    if (EDGE) {
        // Per-edge head scores for this tile's 4 heads -> g_S.
        const float scale = 0.17677669529663687f;  // 1/sqrt(32)
        #pragma unroll
        for (int mi = 0; mi < 2; ++mi) {
            #pragma unroll
            for (int rh = 0; rh < 2; ++rh) {
                int r  = wm * 32 + mi * 16 + qrow + rh * 8;
                int ge = row0 + r;
                const float* Kr = g_K + (long)Ssrc[r] * DIMC + nbase + wn * 64;
                const float* Qr = g_Q + (long)Sdst[r] * DIMC + nbase + wn * 64;
                #pragma unroll
                for (int h = 0; h < 2; ++h) {
                    float p = 0.0f;
                    #pragma unroll
                    for (int j = 0; j < 4; ++j) {
                        int ni = h * 4 + j;
                        int c  = ni * 8 + quad * 2;
                        float2 kv = *(const float2*)(Kr + c);
                        float2 qv = *(const float2*)(Qr + c);
                        p += acc[mi][ni][rh * 2 + 0] * kv.x * qv.x;
                        p += acc[mi][ni][rh * 2 + 1] * kv.y * qv.y;
                    }
                    p += __shfl_xor_sync(0xffffffffu, p, 1);
                    p += __shfl_xor_sync(0xffffffffu, p, 2);
                    if (quad == 0 && ge < NE) {
                        float sv = fminf(5.0f, fmaxf(-5.0f, p * scale));
                        g_S[(long)ge * NH + (nbase >> 5) + wn * 2 + h] = expf(sv);
                    }
                }
            }
        }
    } else {
        int by = blockIdx.y;
        float* Cout = (by < 2) ? g_Q : (by < 4) ? g_K : g_V;
        int colb = (by & 1) * 128;
        #pragma unroll
        for (int mi = 0; mi < 2; ++mi) {
            #pragma unroll
            for (int ni = 0; ni < 8; ++ni) {
                int r = row0 + wm * 32 + mi * 16 + qrow;
                int c = colb + wn * 64 + ni * 8 + quad * 2;
                if (r < NN)
                    *(float2*)(Cout + (long)r * DIMC + c) =
                        make_float2(acc[mi][ni][0], acc[mi][ni][1]);
                if (r + 8 < NN)
                    *(float2*)(Cout + (long)(r + 8) * DIMC + c) =
                        make_float2(acc[mi][ni][2], acc[mi][ni][3]);
            }
        }
    }
}

// ---------------------------------------------------------------------------
// Scatter: wV[dst] += V[src]*score ; Z[dst,h] += score.  32 edges per block.
// ---------------------------------------------------------------------------
__global__ void scatter_kernel() {
    __shared__ int ssrc[32], sdst[32];
    __shared__ float ssc[32][NH];
    int e0 = blockIdx.x * 32;
    int tid = threadIdx.x;
    if (tid < 32) {
        int ge = e0 + tid;
        ssrc[tid] = (ge < NE) ? g_src[ge] : 0;
        sdst[tid] = (ge < NE) ? g_dst[ge] : 0;
    }
    {
        int el = tid >> 3, h = tid & 7;
        int ge = e0 + el;
        ssc[el][h] = (ge < NE) ? g_S[(long)ge * NH + h] : 0.0f;
    }
    __syncthreads();
    int c = tid;
    int h = c >> 5;
    for (int el = 0; el < 32; ++el) {
        int ge = e0 + el;
        if (ge >= NE) break;
        float s = ssc[el][h];
        atomicAdd(&g_wV[(long)sdst[el] * DIMC + c], g_V[(long)ssrc[el] * DIMC + c] * s);
    }
    {
        int el = tid >> 3, h2 = tid & 7;
        int ge = e0 + el;
        if (ge < NE) atomicAdd(&g_Z[(long)sdst[el] * NH + h2], ssc[el][h2]);
    }
}

// ---------------------------------------------------------------------------
// Residual + BN column stats, then normalize.
// ---------------------------------------------------------------------------
__global__ void resid_stats_kernel(const float* __restrict__ x, float* __restrict__ out) {
    int c = threadIdx.x;
    int r0 = blockIdx.x * 256;
    int rend = min(NN, r0 + 256);
    float s = 0.0f, s2 = 0.0f;
    for (int n = r0; n < rend; ++n) {
        float z = g_Z[(long)n * NH + (c >> 5)] + 1e-6f;
        float h = x[(long)n * DIMC + c] + g_wV[(long)n * DIMC + c] / z;
        out[(long)n * DIMC + c] = h;
        s += h;
        s2 += h * h;
    }
    atomicAdd(&g_cs[c], s);
    atomicAdd(&g_cs2[c], s2);
}

__global__ void bn_norm_kernel(float* __restrict__ out,
                               const float* __restrict__ gamma,
                               const float* __restrict__ beta) {
    long total = (long)NN * DIMC;
    long stride = (long)gridDim.x * blockDim.x;
    const float invN = 1.0f / (float)NN;
    for (long i = (long)blockIdx.x * blockDim.x + threadIdx.x; i < total; i += stride) {
        int c = (int)(i & (DIMC - 1));
        float mean = g_cs[c] * invN;
        float var = g_cs2[c] * invN - mean * mean;
        out[i] = (out[i] - mean) * rsqrtf(var + 1e-5f) * gamma[c] + beta[c];
    }
}

extern "C" void kernel_launch(void* const* d_in, const int* in_sizes, int n_in,
                              void* d_out, int out_size) {
    const float* x     = (const float*)d_in[0];
    const float* ea    = (const float*)d_in[1];
    const float* WQ    = (const float*)d_in[2];
    const float* WK    = (const float*)d_in[3];
    const float* WE    = (const float*)d_in[4];
    const float* WV    = (const float*)d_in[5];
    const float* gamma = (const float*)d_in[6];
    const float* beta  = (const float*)d_in[7];
    const long long* eidx = (const long long*)d_in[8];
    float* out = (float*)d_out;

    zero_kernel<<<1024, 256>>>();
    cvt_idx_kernel<<<512, 256>>>(eidx);
    prep_w_kernel<<<1024, 256>>>(WQ, WK, WV, WE);

    // QKV: C[100000,768] -> 782 x 6 tiles of 128x128 (A = x, converted in-kernel)
    mma_gemm_kernel<0><<<dim3(782, 6), 256>>>(x);
    // Edge: Eh GEMM + fused score epilogue -> 3907 x 2 tiles
    mma_gemm_kernel<1><<<dim3(3907, 2), 256>>>(ea);

    scatter_kernel<<<(NE + 31) / 32, 256>>>();
    resid_stats_kernel<<<(NN + 255) / 256, 256>>>(x, out);
    bn_norm_kernel<<<2048, 256>>>(out, gamma, beta);
}

// round 6
// speedup vs baseline: 1.4759x; 1.0241x over previous
#include <cuda_runtime.h>
#include <cuda_bf16.h>
#include <math.h>
#include <stdint.h>

#define NN 100000
#define NE 500000
#define DIMC 256
#define NH 8

// Dynamic smem layout (bytes):
//   A stage s (s=0,1): base + s*20480   -> Ah at +0, Al at +10240
//   B stage s:         base + 40960 + s*20480 -> Bh at +0, Bl at +10240
// total 81920 bytes.
#define STAGE_BYTES 20480
#define HALF_BYTES  10240
#define B_BASE      40960
#define DYN_SMEM    81920

// ---------------------------------------------------------------------------
// Device-global scratch (no allocation allowed in kernel_launch)
// ---------------------------------------------------------------------------
__device__ float g_Q[NN * DIMC];
__device__ float g_K[NN * DIMC];
__device__ float g_V[NN * DIMC];
__device__ float g_wV[NN * DIMC];
__device__ float g_Z[NN * NH];
__device__ float g_S[NE * NH];
__device__ float g_cs[DIMC];
__device__ float g_cs2[DIMC];
__device__ int g_src[NE];
__device__ int g_dst[NE];
__device__ __nv_bfloat16 g_Wh[768 * DIMC], g_Wl[768 * DIMC];     // [n][k], QKV concat
__device__ __nv_bfloat16 g_WEh[DIMC * DIMC], g_WEl[DIMC * DIMC]; // [n][k]

// ---------------------------------------------------------------------------
// Warp-MMA helpers (portable PTX: ldmatrix + mma.sync + cp.async, sm_80+)
// ---------------------------------------------------------------------------
__device__ __forceinline__ uint32_t smem_u32(const void* p) {
    uint32_t a;
    asm("{ .reg .u64 t; cvta.to.shared.u64 t, %1; cvt.u32.u64 %0, t; }"
        : "=r"(a) : "l"(p));
    return a;
}
__device__ __forceinline__ void ldsm_x4(uint32_t* r, uint32_t addr) {
    asm volatile("ldmatrix.sync.aligned.m8n8.x4.shared.b16 {%0,%1,%2,%3}, [%4];"
                 : "=r"(r[0]), "=r"(r[1]), "=r"(r[2]), "=r"(r[3]) : "r"(addr));
}
__device__ __forceinline__ void ldsm_x2(uint32_t* r, uint32_t addr) {
    asm volatile("ldmatrix.sync.aligned.m8n8.x2.shared.b16 {%0,%1}, [%2];"
                 : "=r"(r[0]), "=r"(r[1]) : "r"(addr));
}
__device__ __forceinline__ void mma_bf16(float* d, const uint32_t* a, const uint32_t* b) {
    asm volatile(
        "mma.sync.aligned.m16n8k16.row.col.f32.bf16.bf16.f32 "
        "{%0,%1,%2,%3}, {%4,%5,%6,%7}, {%8,%9}, {%0,%1,%2,%3};"
        : "+f"(d[0]), "+f"(d[1]), "+f"(d[2]), "+f"(d[3])
        : "r"(a[0]), "r"(a[1]), "r"(a[2]), "r"(a[3]), "r"(b[0]), "r"(b[1]));
}
__device__ __forceinline__ uint32_t packbf(__nv_bfloat16 a, __nv_bfloat16 b) {
    __nv_bfloat162 t = __halves2bfloat162(a, b);
    return *(uint32_t*)&t;
}
__device__ __forceinline__ void cp_async16(uint32_t saddr, const void* gptr) {
    asm volatile("cp.async.cg.shared.global [%0], [%1], 16;"
                 :: "r"(saddr), "l"(gptr) : "memory");
}
__device__ __forceinline__ void cp_commit() {
    asm volatile("cp.async.commit_group;" ::: "memory");
}
__device__ __forceinline__ void cp_wait0() {
    asm volatile("cp.async.wait_group 0;" ::: "memory");
}

// ---------------------------------------------------------------------------
// Zero atomically-updated accumulators.
// ---------------------------------------------------------------------------
__global__ void zero_kernel() {
    long total = (long)NN * DIMC + (long)NN * NH;
    long stride = (long)gridDim.x * blockDim.x;
    for (long i = (long)blockIdx.x * blockDim.x + threadIdx.x; i < total; i += stride) {
        if (i < (long)NN * DIMC) g_wV[i] = 0.0f;
        else                     g_Z[i - (long)NN * DIMC] = 0.0f;
    }
    if (blockIdx.x == 0 && threadIdx.x < DIMC) {
        g_cs[threadIdx.x]  = 0.0f;
        g_cs2[threadIdx.x] = 0.0f;
    }
}

// ---------------------------------------------------------------------------
// edge_index -> int32 src/dst (handles int64 or int32 payload, deterministic)
// ---------------------------------------------------------------------------
__global__ void cvt_idx_kernel(const long long* __restrict__ e64) {
    const int* e32 = (const int*)e64;
    bool is64 = true;
    #pragma unroll
    for (int i = 0; i < 64; ++i)
        if ((e64[i] >> 32) != 0) is64 = false;
    long stride = (long)gridDim.x * blockDim.x;
    for (long e = (long)blockIdx.x * blockDim.x + threadIdx.x; e < NE; e += stride) {
        if (is64) { g_src[e] = (int)e64[e]; g_dst[e] = (int)e64[NE + e]; }
        else      { g_src[e] = e32[e];      g_dst[e] = e32[NE + e];      }
    }
}

// ---------------------------------------------------------------------------
// Weights transposed into B-operand layout [n][k], split hi/lo. (Tiny.)
// ---------------------------------------------------------------------------
__global__ void prep_w_kernel(const float* __restrict__ WQ, const float* __restrict__ WK,
                              const float* __restrict__ WV, const float* __restrict__ WE) {
    int i = blockIdx.x * 256 + threadIdx.x;   // 0 .. 1024*256-1
    if (i < 768 * DIMC) {
        int n = i >> 8;
        int k = i & 255;
        int m = n >> 8, nn = n & 255;
        const float* W = (m == 0) ? WQ : (m == 1) ? WK : WV;
        float v = W[k * DIMC + nn];
        __nv_bfloat16 h = __float2bfloat16(v);
        g_Wh[i] = h;
        g_Wl[i] = __float2bfloat16(v - __bfloat162float(h));
    } else {
        int j = i - 768 * DIMC;
        int n = j >> 8, k = j & 255;
        float v = WE[k * DIMC + n];
        __nv_bfloat16 h = __float2bfloat16(v);
        g_WEh[j] = h;
        g_WEl[j] = __float2bfloat16(v - __bfloat162float(h));
    }
}

// ---------------------------------------------------------------------------
// Warp-MMA split-bf16 GEMM, 128x128 block tile, K=256 in 8 chunks of 32.
// TWO-STAGE double-buffered smem pipeline:
//   iter kc: STS A(kc)->stage kc&1 ; wait B(kc) ; bar ;
//            issue B(kc+1) cp.async + LDG-prefetch A(kc+1) ; MMA(kc)
// 8 warps in 4(M) x 2(N); each warp computes 32x64 via m16n8k16 bf16 mma.
// 3 MMAs per (mi,ni,k16): Ah*Bh + Ah*Bl + Al*Bh  (fp32 accumulate).
// EDGE=0: writes Q/K/V.  EDGE=1: per-edge head-score epilogue -> g_S.
// ---------------------------------------------------------------------------
template<int EDGE>
__global__ void __launch_bounds__(256, 2) mma_gemm_kernel(const float* __restrict__ Asrc) {
    extern __shared__ __align__(16) char dsm[];
    __shared__ int Ssrc[128], Sdst[128];

    const int tid  = threadIdx.x;
    const int wid  = tid >> 5;
    const int lane = tid & 31;
    const int wm   = wid & 3;
    const int wn   = wid >> 2;
    const int quad = lane & 3;
    const int qrow = lane >> 2;

    const int row0  = blockIdx.x * 128;
    const int nbase = blockIdx.y * 128;
    const int Mtot  = EDGE ? NE : NN;

    if (EDGE && tid < 128) {
        int ge = row0 + tid;
        if (ge > NE - 1) ge = NE - 1;
        Ssrc[tid] = g_src[ge];
        Sdst[tid] = g_dst[ge];
    }

    const float4* A4 = (const float4*)Asrc;
    const uint4* Bh4 = EDGE ? (const uint4*)g_WEh : (const uint4*)g_Wh;
    const uint4* Bl4 = EDGE ? (const uint4*)g_WEl : (const uint4*)g_Wl;

    float acc[2][8][4] = {};

    const uint32_t base = smem_u32(dsm);
    const uint32_t aOff = (uint32_t)((wm * 32 + (lane & 15)) * 80 + (lane >> 4) * 16);
    const uint32_t bOffRow = (uint32_t)((wn * 64 + (lane & 7)) * 80 + ((lane >> 3) & 1) * 16);

    // Per-thread fixed staging coords. A: row = (tid + l*256)>>3, c4 = tid&7.
    const int aRow[4] = { (tid + 0) >> 3, (tid + 256) >> 3, (tid + 512) >> 3, (tid + 768) >> 3 };
    const int aC4 = tid & 7;
    long aRowG[4];
    #pragma unroll
    for (int l = 0; l < 4; ++l) aRowG[l] = min(row0 + aRow[l], Mtot - 1);

    // B staging coords: idx = tid + l*256; sel = idx>>9; w = idx&511.
    // gsrc row = nbase + (w>>2), c4 = w&3.

    // ---- prologue: prefetch A(0) regs; issue cp.async B(0) -> stage 0 ----
    float4 aPre[4];
    #pragma unroll
    for (int l = 0; l < 4; ++l) aPre[l] = A4[aRowG[l] * 64 + 0 + aC4];
    {
        uint32_t bB = base + B_BASE;   // stage 0
        #pragma unroll
        for (int l = 0; l < 4; ++l) {
            int idx = tid + l * 256;
            int sel = idx >> 9;
            int w   = idx & 511;
            int row = w >> 2;
            int c4  = w & 3;
            const uint4* gsrc = (sel ? Bl4 : Bh4) + (long)(nbase + row) * 32 + 0 + c4;
            cp_async16(bB + (uint32_t)(sel * HALF_BYTES + row * 80 + c4 * 16), gsrc);
        }
        cp_commit();
    }

    for (int kc = 0; kc < 8; ++kc) {
        const int st = kc & 1;
        const uint32_t aBase = base + st * STAGE_BYTES;
        const uint32_t bBase = base + B_BASE + st * STAGE_BYTES;
        __nv_bfloat16* sAh = (__nv_bfloat16*)(dsm + st * STAGE_BYTES);
        __nv_bfloat16* sAl = (__nv_bfloat16*)(dsm + st * STAGE_BYTES + HALF_BYTES);

        // STS A(kc) into stage st (readers of this stage finished at sync(kc-1)).
        #pragma unroll
        for (int l = 0; l < 4; ++l) {
            float4 v = aPre[l];
            __nv_bfloat16 h0 = __float2bfloat16(v.x);
            __nv_bfloat16 h1 = __float2bfloat16(v.y);
            __nv_bfloat16 h2 = __float2bfloat16(v.z);
            __nv_bfloat16 h3 = __float2bfloat16(v.w);
            __nv_bfloat16 l0 = __float2bfloat16(v.x - __bfloat162float(h0));
            __nv_bfloat16 l1 = __float2bfloat16(v.y - __bfloat162float(h1));
            __nv_bfloat16 l2 = __float2bfloat16(v.z - __bfloat162float(h2));
            __nv_bfloat16 l3 = __float2bfloat16(v.w - __bfloat162float(h3));
            int row = aRow[l];
            *(uint2*)(sAh + row * 40 + aC4 * 4) = make_uint2(packbf(h0, h1), packbf(h2, h3));
            *(uint2*)(sAl + row * 40 + aC4 * 4) = make_uint2(packbf(l0, l1), packbf(l2, l3));
        }

        cp_wait0();        // B(kc) landed (issued a full iteration ago)
        __syncthreads();   // all warps done with MMA(kc-1); stages coherent

        // Issue B(kc+1) into the other stage; its old readers just finished.
        if (kc < 7) {
            uint32_t bBn = base + B_BASE + (st ^ 1) * STAGE_BYTES;
            #pragma unroll
            for (int l = 0; l < 4; ++l) {
                int idx = tid + l * 256;
                int sel = idx >> 9;
                int w   = idx & 511;
                int row = w >> 2;
                int c4  = w & 3;
                const uint4* gsrc = (sel ? Bl4 : Bh4) + (long)(nbase + row) * 32 + (kc + 1) * 4 + c4;
                cp_async16(bBn + (uint32_t)(sel * HALF_BYTES + row * 80 + c4 * 16), gsrc);
            }
            cp_commit();
            // Prefetch A(kc+1): LDGs fly during MMA(kc).
            #pragma unroll
            for (int l = 0; l < 4; ++l)
                aPre[l] = A4[aRowG[l] * 64 + (kc + 1) * 8 + aC4];
        }

        // ---- MMA on stage st ----
        #pragma unroll
        for (int s = 0; s < 2; ++s) {
            uint32_t ah[2][4], al[2][4];
            #pragma unroll
            for (int mi = 0; mi < 2; ++mi) {
                uint32_t o = aOff + (uint32_t)(mi * 16 * 80 + s * 32);
                ldsm_x4(ah[mi], aBase + o);
                ldsm_x4(al[mi], aBase + HALF_BYTES + o);
            }
            #pragma unroll
            for (int ni = 0; ni < 8; ++ni) {
                uint32_t bo = bOffRow + (uint32_t)(ni * 8 * 80 + s * 32);
                uint32_t bh[2], bl[2];
                ldsm_x2(bh, bBase + bo);
                ldsm_x2(bl, bBase + HALF_BYTES + bo);
                #pragma unroll
                for (int mi = 0; mi < 2; ++mi) {
                    mma_bf16(acc[mi][ni], ah[mi], bh);
                    mma_bf16(acc[mi][ni], ah[mi], bl);
                    mma_bf16(acc[mi][ni], al[mi], bh);
                }
            }
        }
    }

    if (EDGE) {
        // Per-edge head scores for this tile's 4 heads -> g_S.
        const float scale = 0.17677669529663687f;  // 1/sqrt(32)
        #pragma unroll
        for (int mi = 0; mi < 2; ++mi) {
            #pragma unroll
            for (int rh = 0; rh < 2; ++rh) {
                int r  = wm * 32 + mi * 16 + qrow + rh * 8;
                int ge = row0 + r;
                const float* Kr = g_K + (long)Ssrc[r] * DIMC + nbase + wn * 64;
                const float* Qr = g_Q + (long)Sdst[r] * DIMC + nbase + wn * 64;
                #pragma unroll
                for (int h = 0; h < 2; ++h) {
                    float p = 0.0f;
                    #pragma unroll
                    for (int j = 0; j < 4; ++j) {
                        int ni = h * 4 + j;
                        int c  = ni * 8 + quad * 2;
                        float2 kv = *(const float2*)(Kr + c);
                        float2 qv = *(const float2*)(Qr + c);
                        p += acc[mi][ni][rh * 2 + 0] * kv.x * qv.x;
                        p += acc[mi][ni][rh * 2 + 1] * kv.y * qv.y;
                    }
                    p += __shfl_xor_sync(0xffffffffu, p, 1);
                    p += __shfl_xor_sync(0xffffffffu, p, 2);
                    if (quad == 0 && ge < NE) {
                        float sv = fminf(5.0f, fmaxf(-5.0f, p * scale));
                        g_S[(long)ge * NH + (nbase >> 5) + wn * 2 + h] = expf(sv);
                    }
                }
            }
        }
    } else {
        int by = blockIdx.y;
        float* Cout = (by < 2) ? g_Q : (by < 4) ? g_K : g_V;
        int colb = (by & 1) * 128;
        #pragma unroll
        for (int mi = 0; mi < 2; ++mi) {
            #pragma unroll
            for (int ni = 0; ni < 8; ++ni) {
                int r = row0 + wm * 32 + mi * 16 + qrow;
                int c = colb + wn * 64 + ni * 8 + quad * 2;
                if (r < NN)
                    *(float2*)(Cout + (long)r * DIMC + c) =
                        make_float2(acc[mi][ni][0], acc[mi][ni][1]);
                if (r + 8 < NN)
                    *(float2*)(Cout + (long)(r + 8) * DIMC + c) =
                        make_float2(acc[mi][ni][2], acc[mi][ni][3]);
            }
        }
    }
}

// ---------------------------------------------------------------------------
// Scatter: wV[dst] += V[src]*score ; Z[dst,h] += score.  32 edges per block.
// ---------------------------------------------------------------------------
__global__ void scatter_kernel() {
    __shared__ int ssrc[32], sdst[32];
    __shared__ float ssc[32][NH];
    int e0 = blockIdx.x * 32;
    int tid = threadIdx.x;
    if (tid < 32) {
        int ge = e0 + tid;
        ssrc[tid] = (ge < NE) ? g_src[ge] : 0;
        sdst[tid] = (ge < NE) ? g_dst[ge] : 0;
    }
    {
        int el = tid >> 3, h = tid & 7;
        int ge = e0 + el;
        ssc[el][h] = (ge < NE) ? g_S[(long)ge * NH + h] : 0.0f;
    }
    __syncthreads();
    int c = tid;
    int h = c >> 5;
    for (int el = 0; el < 32; ++el) {
        int ge = e0 + el;
        if (ge >= NE) break;
        float s = ssc[el][h];
        atomicAdd(&g_wV[(long)sdst[el] * DIMC + c], g_V[(long)ssrc[el] * DIMC + c] * s);
    }
    {
        int el = tid >> 3, h2 = tid & 7;
        int ge = e0 + el;
        if (ge < NE) atomicAdd(&g_Z[(long)sdst[el] * NH + h2], ssc[el][h2]);
    }
}

// ---------------------------------------------------------------------------
// Residual + BN column stats, then normalize.
// ---------------------------------------------------------------------------
__global__ void resid_stats_kernel(const float* __restrict__ x, float* __restrict__ out) {
    int c = threadIdx.x;
    int r0 = blockIdx.x * 256;
    int rend = min(NN, r0 + 256);
    float s = 0.0f, s2 = 0.0f;
    for (int n = r0; n < rend; ++n) {
        float z = g_Z[(long)n * NH + (c >> 5)] + 1e-6f;
        float h = x[(long)n * DIMC + c] + g_wV[(long)n * DIMC + c] / z;
        out[(long)n * DIMC + c] = h;
        s += h;
        s2 += h * h;
    }
    atomicAdd(&g_cs[c], s);
    atomicAdd(&g_cs2[c], s2);
}

__global__ void bn_norm_kernel(float* __restrict__ out,
                               const float* __restrict__ gamma,
                               const float* __restrict__ beta) {
    long total = (long)NN * DIMC;
    long stride = (long)gridDim.x * blockDim.x;
    const float invN = 1.0f / (float)NN;
    for (long i = (long)blockIdx.x * blockDim.x + threadIdx.x; i < total; i += stride) {
        int c = (int)(i & (DIMC - 1));
        float mean = g_cs[c] * invN;
        float var = g_cs2[c] * invN - mean * mean;
        out[i] = (out[i] - mean) * rsqrtf(var + 1e-5f) * gamma[c] + beta[c];
    }
}

extern "C" void kernel_launch(void* const* d_in, const int* in_sizes, int n_in,
                              void* d_out, int out_size) {
    const float* x     = (const float*)d_in[0];
    const float* ea    = (const float*)d_in[1];
    const float* WQ    = (const float*)d_in[2];
    const float* WK    = (const float*)d_in[3];
    const float* WE    = (const float*)d_in[4];
    const float* WV    = (const float*)d_in[5];
    const float* gamma = (const float*)d_in[6];
    const float* beta  = (const float*)d_in[7];
    const long long* eidx = (const long long*)d_in[8];
    float* out = (float*)d_out;

    // Opt-in to >48KB dynamic smem (attribute set, not an allocation).
    static bool attr_done = false;
    if (!attr_done) {
        cudaFuncSetAttribute(mma_gemm_kernel<0>,
                             cudaFuncAttributeMaxDynamicSharedMemorySize, DYN_SMEM);
        cudaFuncSetAttribute(mma_gemm_kernel<1>,
                             cudaFuncAttributeMaxDynamicSharedMemorySize, DYN_SMEM);
        attr_done = true;
    }

    zero_kernel<<<1024, 256>>>();
    cvt_idx_kernel<<<512, 256>>>(eidx);
    prep_w_kernel<<<1024, 256>>>(WQ, WK, WV, WE);

    // QKV: C[100000,768] -> 782 x 6 tiles of 128x128 (A = x, converted in-kernel)
    mma_gemm_kernel<0><<<dim3(782, 6), 256, DYN_SMEM>>>(x);
    // Edge: Eh GEMM + fused score epilogue -> 3907 x 2 tiles
    mma_gemm_kernel<1><<<dim3(3907, 2), 256, DYN_SMEM>>>(ea);

    scatter_kernel<<<(NE + 31) / 32, 256>>>();
    resid_stats_kernel<<<(NN + 255) / 256, 256>>>(x, out);
    bn_norm_kernel<<<2048, 256>>>(out, gamma, beta);
}